// round 15
// baseline (speedup 1.0000x reference)
#include <cuda_runtime.h>
#include <cuda_fp16.h>
#include <math.h>
#include <stdint.h>

#define TOK   25088      // 8*56*56
#define CDIM  256
#define QKVN  768
#define HIDN  1024
#define HW    56
#define P2    49
#define ASCALE 0.0625f   // 256^-0.5

// ---------------- scratch (device globals; no allocation allowed) ----------
__device__ __half g_h1h[TOK * CDIM];      // LN output (fp16, GEMM A)
__device__ __half g_qkvh[TOK * QKVN];     // qkv projections (fp16, sole copy)
__device__ __half g_attnh[TOK * CDIM];    // attn out, then +lepe in place (fp16)
__device__ float  g_y1[TOK * CDIM];       // residual stream after attn
__device__ __half g_hidh[TOK * HIDN];     // MLP hidden (fp16, from epi)
// transposed fp16 weights, concatenated: [N x K] layouts
#define WT_QKV 0
#define WT_WO  (768*256)
#define WT_W1  (WT_WO + 256*256)
#define WT_W2  (WT_W1 + 1024*256)
__device__ __half g_wt[768*256 + 256*256 + 1024*256 + 256*1024];
__device__ float g_qwin[8 * P2 * 256];
__device__ float g_kwin[8 * P2 * 256];
__device__ int   g_ridx[8 * P2 * 4];

// ---------------- small helpers ---------------------------------------------
__device__ __forceinline__ uint32_t smem_u32(const void* p) {
    uint32_t a;
    asm("{ .reg .u64 t; cvta.to.shared.u64 t, %1; cvt.u32.u64 %0, t; }"
        : "=r"(a) : "l"(p));
    return a;
}
#define CPA16(dst, src) \
    asm volatile("cp.async.cg.shared.global [%0], [%1], 16;" :: "r"(dst), "l"(src))
#define CPA_COMMIT() asm volatile("cp.async.commit_group;" ::: "memory")

__device__ __forceinline__ void mma_f16(float* c, const uint32_t* a, const uint32_t* b) {
    asm volatile(
        "mma.sync.aligned.m16n8k16.row.col.f32.f16.f16.f32 "
        "{%0,%1,%2,%3}, {%4,%5,%6,%7}, {%8,%9}, {%0,%1,%2,%3};"
        : "+f"(c[0]), "+f"(c[1]), "+f"(c[2]), "+f"(c[3])
        : "r"(a[0]), "r"(a[1]), "r"(a[2]), "r"(a[3]), "r"(b[0]), "r"(b[1]));
}

__device__ __forceinline__ void ldsm_x4(uint32_t* r, uint32_t addr) {
    asm volatile("ldmatrix.sync.aligned.m8n8.x4.shared.b16 {%0,%1,%2,%3}, [%4];"
        : "=r"(r[0]), "=r"(r[1]), "=r"(r[2]), "=r"(r[3]) : "r"(addr));
}
__device__ __forceinline__ void ldsm_x2(uint32_t& r0, uint32_t& r1, uint32_t addr) {
    asm volatile("ldmatrix.sync.aligned.m8n8.x2.shared.b16 {%0,%1}, [%2];"
        : "=r"(r0), "=r"(r1) : "r"(addr));
}
__device__ __forceinline__ void ldsm_x2_trans(uint32_t& r0, uint32_t& r1, uint32_t addr) {
    asm volatile("ldmatrix.sync.aligned.m8n8.x2.trans.shared.b16 {%0,%1}, [%2];"
        : "=r"(r0), "=r"(r1) : "r"(addr));
}

__device__ __forceinline__ uint32_t pack_h2(float v0, float v1) {
    __half2 pk = __floats2half2_rn(v0, v1);
    uint32_t r;
    *(__half2*)&r = pk;
    return r;
}

// ---------------- fp16 HMMA GEMM: 128x128 tile, BK=32, cp.async 2-stage -----
// warp grid 2x4 (warp tile 64x32).  A: [M,K] fp16.  Bt: [N,K] fp16.
// Fragment loads via ldmatrix (x4 for A, x2 for B).
// epi: 0 = bias (fp16 out), 1 = bias+GELU (fp16 out), 2 = bias+res (fp32 out)
#define SROW 40   // smem row stride in halves (80B) -> conflict-free frag loads
__global__ __launch_bounds__(256) void gemm_mma_kernel(
    const __half* __restrict__ A, const __half* __restrict__ Bt,
    const float* __restrict__ bias, const float* __restrict__ res,
    float* __restrict__ Cf, __half* __restrict__ Ch,
    int M, int N, int K, int epi)
{
    __shared__ __align__(16) __half sa[2][128][SROW];
    __shared__ __align__(16) __half sb[2][128][SROW];

    const int tid = threadIdx.x;
    const int wid = tid >> 5, l = tid & 31;
    const int wm = wid >> 2, wn = wid & 3;            // warp grid 2x4
    const int m0 = blockIdx.y << 7, n0 = blockIdx.x << 7;
    const int gr = l >> 2, tc = (l & 3) << 1;

    const int lr = tid >> 2, lc = (tid & 3) << 3;     // 64 rows x 4x8 halves
    const __half* Ap0 = A + (size_t)(m0 + lr) * K + lc;
    const __half* Ap1 = A + (size_t)(m0 + lr + 64) * K + lc;
    const __half* Bp0 = Bt + (size_t)(n0 + lr) * K + lc;
    const __half* Bp1 = Bt + (size_t)(n0 + lr + 64) * K + lc;
    const uint32_t sa0 = smem_u32(&sa[0][lr][lc]);
    const uint32_t sa1 = smem_u32(&sa[0][lr + 64][lc]);
    const uint32_t sb0 = smem_u32(&sb[0][lr][lc]);
    const uint32_t sb1 = smem_u32(&sb[0][lr + 64][lc]);
    const uint32_t BUF = 128 * SROW * 2;
    const uint32_t saB = smem_u32(&sa[0][0][0]);
    const uint32_t sbB = smem_u32(&sb[0][0][0]);
    // ldmatrix lane address components
    const int a_row = l & 15, a_colblk = (l >> 4) << 3;    // x4 (16x16 tile)
    const int b_row = l & 7,  b_colblk = ((l >> 3) & 1) << 3; // x2

    float acc[4][4][4];
#pragma unroll
    for (int i = 0; i < 4; i++)
#pragma unroll
        for (int j = 0; j < 4; j++)
#pragma unroll
            for (int v = 0; v < 4; v++) acc[i][j][v] = 0.0f;

    const int nst = K >> 5;
    CPA16(sa0, Ap0); CPA16(sa1, Ap1); CPA16(sb0, Bp0); CPA16(sb1, Bp1);
    CPA_COMMIT();

    int buf = 0;
    for (int s = 0; s < nst; s++) {
        if (s + 1 < nst) {
            int k0 = (s + 1) << 5;
            int ob = (buf ^ 1);
            CPA16(sa0 + ob * BUF, Ap0 + k0);
            CPA16(sa1 + ob * BUF, Ap1 + k0);
            CPA16(sb0 + ob * BUF, Bp0 + k0);
            CPA16(sb1 + ob * BUF, Bp1 + k0);
            CPA_COMMIT();
            asm volatile("cp.async.wait_group 1;" ::: "memory");
        } else {
            asm volatile("cp.async.wait_group 0;" ::: "memory");
        }
        __syncthreads();

        uint32_t bufA = saB + buf * BUF, bufB = sbB + buf * BUF;
#pragma unroll
        for (int kk = 0; kk < 32; kk += 16) {
            uint32_t af[4][4], bfr[4][2];
#pragma unroll
            for (int mi = 0; mi < 4; mi++) {
                int r = (wm << 6) + (mi << 4) + a_row;
                ldsm_x4(af[mi], bufA + (uint32_t)(r * SROW + kk + a_colblk) * 2);
            }
#pragma unroll
            for (int ni = 0; ni < 4; ni++) {
                int r = (wn << 5) + (ni << 3) + b_row;
                ldsm_x2(bfr[ni][0], bfr[ni][1],
                        bufB + (uint32_t)(r * SROW + kk + b_colblk) * 2);
            }
#pragma unroll
            for (int mi = 0; mi < 4; mi++)
#pragma unroll
                for (int ni = 0; ni < 4; ni++)
                    mma_f16(acc[mi][ni], af[mi], bfr[ni]);
        }
        __syncthreads();
        buf ^= 1;
    }

    // ---------------- epilogue ----------------
    float2 bv[4];
#pragma unroll
    for (int ni = 0; ni < 4; ni++)
        bv[ni] = *(const float2*)(bias + n0 + (wn << 5) + (ni << 3) + tc);

#pragma unroll
    for (int mi = 0; mi < 4; mi++) {
#pragma unroll
        for (int h = 0; h < 2; h++) {          // row halves (+0 / +8)
            int row = m0 + (wm << 6) + (mi << 4) + gr + (h << 3);
#pragma unroll
            for (int ni = 0; ni < 4; ni++) {
                int col = n0 + (wn << 5) + (ni << 3) + tc;
                float v0 = acc[mi][ni][h * 2 + 0] + bv[ni].x;
                float v1 = acc[mi][ni][h * 2 + 1] + bv[ni].y;
                if (epi == 2) {
                    float2 r2 = *(const float2*)(res + (size_t)row * N + col);
                    float2 o2;
                    o2.x = v0 + r2.x; o2.y = v1 + r2.y;
                    *(float2*)(Cf + (size_t)row * N + col) = o2;
                } else {
                    if (epi == 1) {
                        v0 = 0.5f * v0 * (1.0f + erff(v0 * 0.7071067811865476f));
                        v1 = 0.5f * v1 * (1.0f + erff(v1 * 0.7071067811865476f));
                    }
                    *(uint32_t*)(Ch + (size_t)row * N + col) = pack_h2(v0, v1);
                }
            }
        }
    }
}

// ---------------- helpers ---------------------------------------------------
__device__ __forceinline__ int win_token(int n, int p, int pix) {
    int wj = p / 7, wi = p % 7;
    int y = wj * 8 + (pix >> 3);
    int x = wi * 8 + (pix & 7);
    return (n * HW + y) * HW + x;
}

// exp(x) for x <= 0 on the FMA pipe (avoids MUFU throughput wall).
__device__ __forceinline__ float fexp(float x) {
    float z = fmaxf(x * 1.4426950408889634f, -120.0f);
    float t = z + 12582912.0f;                       // 1.5*2^23 magic
    int   ni = __float_as_int(t) - __float_as_int(12582912.0f);
    float f = z - (t - 12582912.0f);
    float p = fmaf(f, 0.0013333558f, 0.0096181291f);
    p = fmaf(f, p, 0.0555041087f);
    p = fmaf(f, p, 0.2402265070f);
    p = fmaf(f, p, 0.6931471806f);
    p = fmaf(f, p, 1.0f);
    return p * __int_as_float((ni + 127) << 23);
}

// ---------------- LayerNorm: one warp per token, fp16 output ----------------
__global__ __launch_bounds__(256) void ln_h_kernel(
    const float* __restrict__ x, const float* __restrict__ g,
    const float* __restrict__ b, __half* __restrict__ o)
{
    int w = blockIdx.x * 8 + (threadIdx.x >> 5);
    int lane = threadIdx.x & 31;
    const float* xp = x + (size_t)w * 256 + lane * 8;
    float4 a = *(const float4*)xp;
    float4 c = *(const float4*)(xp + 4);
    float s  = a.x + a.y + a.z + a.w + c.x + c.y + c.z + c.w;
    float ss = a.x*a.x + a.y*a.y + a.z*a.z + a.w*a.w
             + c.x*c.x + c.y*c.y + c.z*c.z + c.w*c.w;
#pragma unroll
    for (int off = 16; off; off >>= 1) {
        s  += __shfl_xor_sync(~0u, s,  off);
        ss += __shfl_xor_sync(~0u, ss, off);
    }
    float mu  = s * (1.0f / 256.0f);
    float var = ss * (1.0f / 256.0f) - mu * mu;
    float inv = rsqrtf(var + 1e-6f);
    float4 g1 = *(const float4*)(g + lane * 8);
    float4 g2 = *(const float4*)(g + lane * 8 + 4);
    float4 b1 = *(const float4*)(b + lane * 8);
    float4 b2 = *(const float4*)(b + lane * 8 + 4);
    float v[8];
    v[0] = (a.x - mu) * inv * g1.x + b1.x;
    v[1] = (a.y - mu) * inv * g1.y + b1.y;
    v[2] = (a.z - mu) * inv * g1.z + b1.z;
    v[3] = (a.w - mu) * inv * g1.w + b1.w;
    v[4] = (c.x - mu) * inv * g2.x + b2.x;
    v[5] = (c.y - mu) * inv * g2.y + b2.y;
    v[6] = (c.z - mu) * inv * g2.z + b2.z;
    v[7] = (c.w - mu) * inv * g2.w + b2.w;
    uint32_t pk[4];
#pragma unroll
    for (int j = 0; j < 4; j++) pk[j] = pack_h2(v[2*j], v[2*j+1]);
    *(uint4*)(o + (size_t)w * 256 + lane * 8) = *(uint4*)pk;
}

// ---------------- ALL weight transposes in one launch -----------------------
// 768 tiles total: [0,192) qkv, [192,256) wo, [256,512) w1, [512,768) w2
__global__ __launch_bounds__(256) void wtrans_all_kernel(
    const float* __restrict__ qkvw, const float* __restrict__ wow,
    const float* __restrict__ w1,   const float* __restrict__ w2)
{
    __shared__ float tile[32][33];
    int t = blockIdx.x;
    const float* w; __half* o; int K, N;
    if (t < 192)      { w = qkvw; o = g_wt + WT_QKV; K = 256;  N = 768;  }
    else if (t < 256) { t -= 192; w = wow; o = g_wt + WT_WO; K = 256;  N = 256;  }
    else if (t < 512) { t -= 256; w = w1;  o = g_wt + WT_W1; K = 256;  N = 1024; }
    else              { t -= 512; w = w2;  o = g_wt + WT_W2; K = 1024; N = 256;  }
    int ktiles = K >> 5;
    int kb = (t % ktiles) << 5, nb = (t / ktiles) << 5;
    int tx = threadIdx.x & 31, ty = threadIdx.x >> 5;   // 32 x 8
#pragma unroll
    for (int i = 0; i < 4; i++)
        tile[ty + (i << 3)][tx] = w[(size_t)(kb + ty + (i << 3)) * N + nb + tx];
    __syncthreads();
#pragma unroll
    for (int i = 0; i < 4; i++)
        o[(size_t)(nb + ty + (i << 3)) * K + kb + tx] =
            __float2half_rn(tile[tx][ty + (i << 3)]);
}

// ---------------- per-window q/k means (fp16 in, fp32 out) ------------------
__global__ __launch_bounds__(512) void winmean_kernel()
{
    int n = blockIdx.x / P2, p = blockIdx.x % P2;
    int c = threadIdx.x;   // 0..511: q channels 0..255, k channels 256..511
    float s = 0.0f;
#pragma unroll 4
    for (int pix = 0; pix < 64; pix++)
        s += __half2float(g_qkvh[(size_t)win_token(n, p, pix) * QKVN + c]);
    s *= (1.0f / 64.0f);
    if (c < 256) g_qwin[(n * P2 + p) * 256 + c] = s;
    else         g_kwin[(n * P2 + p) * 256 + (c - 256)] = s;
}

// ---------------- routing logits + top-4 (warp-uniform shfl) ----------------
__global__ __launch_bounds__(256) void topk_kernel()
{
    int p = blockIdx.x, n = blockIdx.y;
    __shared__ float qs[256];
    __shared__ float lg[64];
    int tid = threadIdx.x;
    qs[tid] = g_qwin[(n * P2 + p) * 256 + tid];
    __syncthreads();
    int j = tid >> 2, part = tid & 3;
    int jc = j < P2 ? j : P2 - 1;            // clamp: keep all lanes convergent
    {
        const float* kw = &g_kwin[(n * P2 + jc) * 256 + (part << 6)];
        const float* qq = &qs[part << 6];
        float s = 0.0f;
#pragma unroll 16
        for (int cc = 0; cc < 64; cc++) s = fmaf(qq[cc], kw[cc], s);
        s += __shfl_xor_sync(~0u, s, 1);
        s += __shfl_xor_sync(~0u, s, 2);
        if (part == 0 && j < P2) lg[j] = s;
    }
    __syncthreads();
    if (tid == 0) {
        int sel[4];
        for (int t = 0; t < 4; t++) {
            float best = -1e30f; int bi = 0;
            for (int jj = 0; jj < P2; jj++) {
                bool used = false;
                for (int u = 0; u < t; u++) if (sel[u] == jj) used = true;
                float v = lg[jj];
                if (!used && v > best) { best = v; bi = jj; }
            }
            sel[t] = bi;
            g_ridx[(n * P2 + p) * 4 + t] = bi;
        }
    }
}

// ---------------- flash attention, fp16 HMMA: block per (n,p), warp = head --
// KV smem: [64 keys][520 ch-padded]: cols 0..255 = K, 256..511 = V (row-major).
// V B-fragments via ldmatrix.x2.trans (no explicit transpose pass).
#define KV_STRIDE 520
#define ATTN_SMEM (64 * KV_STRIDE * 2)
__global__ __launch_bounds__(256) void attn_kernel()
{
    extern __shared__ __align__(16) char dyn[];
    __half* kv = (__half*)dyn;
    __shared__ int selw[4];

    const int n = blockIdx.x / P2, p = blockIdx.x % P2;
    const int tid = threadIdx.x;
    const int m = tid >> 5;            // head
    const int l = tid & 31;
    const int gr = l >> 2, tc = (l & 3) << 1;
    const uint32_t kvb = smem_u32(kv);
    const int lm_row = ((l >> 3) & 1) * 8 + (l & 7);

    if (tid < 4) selw[tid] = g_ridx[(n * P2 + p) * 4 + tid];

    // ---- Q fragments (64q x 32ch per head), pre-scaled by ASCALE ----
    uint32_t qa[4][2][4];
    const __half2 scl = __float2half2_rn(ASCALE);
#pragma unroll
    for (int mi = 0; mi < 4; mi++) {
        int r0 = (mi << 4) + gr;
        int t0 = win_token(n, p, r0);
        int t1 = win_token(n, p, r0 + 8);
#pragma unroll
        for (int kk = 0; kk < 2; kk++) {
            int ch = (m << 5) + (kk << 4) + tc;
            __half2 h0 = *(const __half2*)&g_qkvh[(size_t)t0 * QKVN + ch];
            __half2 h1 = *(const __half2*)&g_qkvh[(size_t)t1 * QKVN + ch];
            __half2 h2 = *(const __half2*)&g_qkvh[(size_t)t0 * QKVN + ch + 8];
            __half2 h3 = *(const __half2*)&g_qkvh[(size_t)t1 * QKVN + ch + 8];
            h0 = __hmul2(h0, scl); h1 = __hmul2(h1, scl);
            h2 = __hmul2(h2, scl); h3 = __hmul2(h3, scl);
            *(__half2*)&qa[mi][kk][0] = h0;
            *(__half2*)&qa[mi][kk][1] = h1;
            *(__half2*)&qa[mi][kk][2] = h2;
            *(__half2*)&qa[mi][kk][3] = h3;
        }
    }

    float oc[4][4][4];
#pragma unroll
    for (int a = 0; a < 4; a++)
#pragma unroll
        for (int b = 0; b < 4; b++)
#pragma unroll
            for (int c = 0; c < 4; c++) oc[a][b][c] = 0.0f;
    float mrow[4][2], lrow[4][2];
#pragma unroll
    for (int a = 0; a < 4; a++) {
        mrow[a][0] = mrow[a][1] = -1e30f;
        lrow[a][0] = lrow[a][1] = 0.0f;
    }

    for (int wl = 0; wl < 4; wl++) {
        __syncthreads();                       // selw ready / prev window done
        int sw = selw[wl];
        int swy = (sw / 7) << 3, swx = (sw % 7) << 3;
        // ---- cooperative load: K||V [64 rows][512 ch] coalesced uint4 ----
#pragma unroll
        for (int i = 0; i < 16; i++) {
            int c = tid + (i << 8);            // 0..4095 uint4 slots
            int row = c >> 6, ch8 = (c & 63) << 3;
            int t = (n * HW + swy + (row >> 3)) * HW + swx + (row & 7);
            *(uint4*)&kv[row * KV_STRIDE + ch8] =
                *(const uint4*)&g_qkvh[(size_t)t * QKVN + 256 + ch8];
        }
        __syncthreads();

        // ---- 4 subchunks of 16 keys, online softmax ----
#pragma unroll
        for (int t = 0; t < 4; t++) {
            int key0 = t << 4;
            uint32_t kb[2][2][2];
#pragma unroll
            for (int ni = 0; ni < 2; ni++)
#pragma unroll
                for (int kk = 0; kk < 2; kk++) {
                    int base = (key0 + (ni << 3) + gr) * KV_STRIDE
                             + (m << 5) + (kk << 4) + tc;
                    kb[ni][kk][0] = *(const uint32_t*)&kv[base];
                    kb[ni][kk][1] = *(const uint32_t*)&kv[base + 8];
                }
            uint32_t paf[4][4];
#pragma unroll
            for (int mi = 0; mi < 4; mi++) {
                float s4[2][4];
#pragma unroll
                for (int ni = 0; ni < 2; ni++)
#pragma unroll
                    for (int j = 0; j < 4; j++) s4[ni][j] = 0.0f;
#pragma unroll
                for (int kk = 0; kk < 2; kk++)
#pragma unroll
                    for (int ni = 0; ni < 2; ni++)
                        mma_f16(s4[ni], qa[mi][kk], kb[ni][kk]);
                float mx0 = fmaxf(fmaxf(s4[0][0], s4[0][1]), fmaxf(s4[1][0], s4[1][1]));
                float mx1 = fmaxf(fmaxf(s4[0][2], s4[0][3]), fmaxf(s4[1][2], s4[1][3]));
#pragma unroll
                for (int off = 1; off <= 2; off <<= 1) {
                    mx0 = fmaxf(mx0, __shfl_xor_sync(~0u, mx0, off));
                    mx1 = fmaxf(mx1, __shfl_xor_sync(~0u, mx1, off));
                }
                float mn0 = fmaxf(mrow[mi][0], mx0);
                float mn1 = fmaxf(mrow[mi][1], mx1);
                float cr0 = fexp(mrow[mi][0] - mn0);
                float cr1 = fexp(mrow[mi][1] - mn1);
                mrow[mi][0] = mn0; mrow[mi][1] = mn1;
                float e00 = fexp(s4[0][0] - mn0), e01 = fexp(s4[0][1] - mn0);
                float e02 = fexp(s4[0][2] - mn1), e03 = fexp(s4[0][3] - mn1);
                float e10 = fexp(s4[1][0] - mn0), e11 = fexp(s4[1][1] - mn0);
                float e12 = fexp(s4[1][2] - mn1), e13 = fexp(s4[1][3] - mn1);
                float sm0 = e00 + e01 + e10 + e11;
                float sm1 = e02 + e03 + e12 + e13;
#pragma unroll
                for (int off = 1; off <= 2; off <<= 1) {
                    sm0 += __shfl_xor_sync(~0u, sm0, off);
                    sm1 += __shfl_xor_sync(~0u, sm1, off);
                }
                lrow[mi][0] = lrow[mi][0] * cr0 + sm0;
                lrow[mi][1] = lrow[mi][1] * cr1 + sm1;
#pragma unroll
                for (int ni = 0; ni < 4; ni++) {
                    oc[mi][ni][0] *= cr0; oc[mi][ni][1] *= cr0;
                    oc[mi][ni][2] *= cr1; oc[mi][ni][3] *= cr1;
                }
                paf[mi][0] = pack_h2(e00, e01);
                paf[mi][1] = pack_h2(e02, e03);
                paf[mi][2] = pack_h2(e10, e11);
                paf[mi][3] = pack_h2(e12, e13);
            }
            // ---- V B-fragments straight from row-major V via ldmatrix.trans
            uint32_t vb[4][2];
#pragma unroll
            for (int ni = 0; ni < 4; ni++) {
                uint32_t addr = kvb +
                    (uint32_t)(((key0 + lm_row) * KV_STRIDE) +
                               256 + (m << 5) + (ni << 3)) * 2;
                ldsm_x2_trans(vb[ni][0], vb[ni][1], addr);
            }
#pragma unroll
            for (int mi = 0; mi < 4; mi++)
#pragma unroll
                for (int ni = 0; ni < 4; ni++)
                    mma_f16(oc[mi][ni], paf[mi], vb[ni]);
        }
    }

    // ---- write O (fp16, pre-lepe) ----
#pragma unroll
    for (int mi = 0; mi < 4; mi++) {
#pragma unroll
        for (int h = 0; h < 2; h++) {
            int row = (mi << 4) + gr + (h << 3);
            int tok = win_token(n, p, row);
            float inv = 1.0f / lrow[mi][h];
#pragma unroll
            for (int ni = 0; ni < 4; ni++) {
                uint32_t pk = pack_h2(oc[mi][ni][h * 2 + 0] * inv,
                                      oc[mi][ni][h * 2 + 1] * inv);
                *(uint32_t*)&g_attnh[(size_t)tok * 256 + (m << 5) + (ni << 3) + tc] = pk;
            }
        }
    }
}

// ---------------- depthwise 5x5 lepe, smem-tiled halo, add in place ---------
// block: (chgroup 0..3 [64 ch], n*49+p). Halo tile 12x12x64 fp16 in smem.
#define LP_STRIDE 66   // halves per pixel row in smem (conflict-free compute)
__global__ __launch_bounds__(256) void lepe_kernel(
    const float* __restrict__ w, const float* __restrict__ b)
{
    __shared__ __half vs[144 * LP_STRIDE];
    __shared__ float ws[25 * 64];
    int cg = blockIdx.x;                  // channel group (64 ch)
    int np = blockIdx.y;
    int n = np / P2, p = np % P2;
    int wy = (p / 7) << 3, wx = (p % 7) << 3;
    int tid = threadIdx.x;
    int c64 = cg << 6;

    // stage weights (25 taps x 64 ch)
    for (int i = tid; i < 25 * 64; i += 256)
        ws[i] = w[(i >> 6) * 256 + c64 + (i & 63)];
    // stage halo v: 144 pixels x 64 ch (zero out-of-image)
    for (int i = tid; i < 144 * 8; i += 256) {
        int pix = i >> 3, ck = (i & 7) << 3;
        int y = wy + pix / 12 - 2, x = wx + pix % 12 - 2;
        uint4 v = {0u, 0u, 0u, 0u};
        if ((unsigned)y < 56u && (unsigned)x < 56u)
            v = *(const uint4*)&g_qkvh[(size_t)((n * 56 + y) * 56 + x) * QKVN
                                       + 512 + c64 + ck];
        uint32_t* dst = (uint32_t*)&vs[pix * LP_STRIDE + ck];
        dst[0] = v.x; dst[1] = v.y; dst[2] = v.z; dst[3] = v.w;
    }
    __syncthreads();

    int pix = tid >> 2, c0 = (tid & 3) << 4;       // out pixel, 16 ch
    int py = pix >> 3, px = pix & 7;
    float acc[16];
#pragma unroll
    for (int j = 0; j < 16; j++) acc[j] = b[c64 + c0 + j];
#pragma unroll
    for (int dy = 0; dy < 5; dy++)
#pragma unroll
        for (int dx = 0; dx < 5; dx++) {
            const __half* vp = &vs[((py + dy) * 12 + px + dx) * LP_STRIDE + c0];
            const float* wp = &ws[(dy * 5 + dx) * 64 + c0];
#pragma unroll
            for (int j2 = 0; j2 < 8; j2++) {
                float2 vv = __half22float2(*(const __half2*)&vp[j2 * 2]);
                acc[2*j2]   = fmaf(vv.x, wp[2*j2],   acc[2*j2]);
                acc[2*j2+1] = fmaf(vv.y, wp[2*j2+1], acc[2*j2+1]);
            }
        }

    int tok = (n * 56 + wy + py) * 56 + wx + px;
    __half* op = &g_attnh[(size_t)tok * 256 + c64 + c0];
    uint4 cur0 = *(uint4*)op;                      // 8 halves
    uint4 cur1 = *(uint4*)(op + 8);
    __half2 ch[8];
    *(uint4*)&ch[0] = cur0;
    *(uint4*)&ch[4] = cur1;
    uint32_t pk[8];
#pragma unroll
    for (int j2 = 0; j2 < 8; j2++) {
        float2 cv = __half22float2(ch[j2]);
        pk[j2] = pack_h2(cv.x + acc[2*j2], cv.y + acc[2*j2+1]);
    }
    *(uint4*)op = *(uint4*)&pk[0];
    *(uint4*)(op + 8) = *(uint4*)&pk[4];
}

// ---------------- launch ----------------------------------------------------
extern "C" void kernel_launch(void* const* d_in, const int* in_sizes, int n_in,
                              void* d_out, int out_size)
{
    const float* x     = (const float*)d_in[0];
    const float* ln1g  = (const float*)d_in[1];
    const float* ln1b  = (const float*)d_in[2];
    const float* qkvw  = (const float*)d_in[3];
    const float* qkvb  = (const float*)d_in[4];
    const float* lepew = (const float*)d_in[5];
    const float* lepeb = (const float*)d_in[6];
    const float* wow   = (const float*)d_in[7];
    const float* wob   = (const float*)d_in[8];
    const float* ln2g  = (const float*)d_in[9];
    const float* ln2b  = (const float*)d_in[10];
    const float* w1    = (const float*)d_in[11];
    const float* b1    = (const float*)d_in[12];
    const float* w2    = (const float*)d_in[13];
    const float* b2    = (const float*)d_in[14];

    __half *h1h, *qkvh, *attnh, *hidh, *wt;
    float *y1;
    cudaGetSymbolAddress((void**)&h1h,   g_h1h);
    cudaGetSymbolAddress((void**)&qkvh,  g_qkvh);
    cudaGetSymbolAddress((void**)&attnh, g_attnh);
    cudaGetSymbolAddress((void**)&y1,    g_y1);
    cudaGetSymbolAddress((void**)&hidh,  g_hidh);
    cudaGetSymbolAddress((void**)&wt,    g_wt);

    cudaFuncSetAttribute(attn_kernel,
                         cudaFuncAttributeMaxDynamicSharedMemorySize, ATTN_SMEM);

    // weight transpose+convert (single launch, 768 tiles)
    wtrans_all_kernel<<<768, 256>>>(qkvw, wow, w1, w2);

    // 1. LN1 -> fp16
    ln_h_kernel<<<3136, 256>>>(x, ln1g, ln1b, h1h);
    // 2. qkv projection (fp16 out only)
    gemm_mma_kernel<<<dim3(6, 196), 256>>>(h1h, wt + WT_QKV, qkvb, nullptr,
                                           nullptr, qkvh, TOK, 768, 256, 0);
    // 3-4. routing (fp16 reads, fp32 accum)
    winmean_kernel<<<392, 512>>>();
    topk_kernel<<<dim3(49, 8), 256>>>();
    // 5. gathered window attention (fp16 HMMA flash, ldmatrix.trans V) -> fp16
    attn_kernel<<<392, 256, ATTN_SMEM>>>();
    // 6. lepe depthwise conv (smem halo tile) + add in place (fp16)
    lepe_kernel<<<dim3(4, 392), 256>>>(lepew, lepeb);
    // 7. output projection + residual with x -> fp32 y1
    gemm_mma_kernel<<<dim3(2, 196), 256>>>(attnh, wt + WT_WO, wob, x,
                                           y1, nullptr, TOK, 256, 256, 2);
    // 8. LN2 -> fp16
    ln_h_kernel<<<3136, 256>>>(y1, ln2g, ln2b, h1h);
    // 9. MLP up + exact GELU, fp16 out
    gemm_mma_kernel<<<dim3(8, 196), 256>>>(h1h, wt + WT_W1, b1, nullptr,
                                           nullptr, hidh, TOK, 1024, 256, 1);
    // 10. MLP down + residual -> d_out
    gemm_mma_kernel<<<dim3(2, 196), 256>>>(hidh, wt + WT_W2, b2, y1,
                                           (float*)d_out, nullptr, TOK, 256, 1024, 2);
}